// round 11
// baseline (speedup 1.0000x reference)
#include <cuda_runtime.h>
#include <cuda_fp16.h>
#include <cuda_bf16.h>

#define N_NODES 100000
#define N_EDGES 1600000
#define CH      128   // in = out channels
#define N_SBLKS ((N_NODES + 1023) / 1024)   // 98

// ---------------- static scratch (no allocations allowed) ----------------
__device__ __half g_y16[(size_t)N_NODES * CH];   // fp16(x @ W^T)
__device__ __half g_h1[(size_t)N_NODES * CH];    // after hop 1
__device__ __half g_w16[CH * CH];
__device__ int    g_deg[N_NODES];
__device__ int    g_off[N_NODES + 1];
__device__ int    g_cursor[N_NODES];
__device__ int    g_srcs[N_EDGES];
__device__ int    g_part[128];
__device__ int    g_idx64;   // 1 if edge_index is int64, 0 if int32

// ---------------- prep: zero degrees + dtype detect + W -> fp16 ----------------
#define ZB ((N_NODES + 255) / 256)          // 391
#define WB ((CH * CH / 2 + 255) / 256)      // 32

__global__ void k_prep(const int* __restrict__ raw, const float* __restrict__ W) {
    if (blockIdx.x < ZB) {
        int i = blockIdx.x * 256 + threadIdx.x;
        if (i < N_NODES) g_deg[i] = 0;
        if (blockIdx.x == 0 && threadIdx.x == 0) {
            int nz = 0;
#pragma unroll
            for (int k = 0; k < 64; k++) {
                if (raw[2 * k + 1] != 0) nz++;
            }
            g_idx64 = (nz == 0) ? 1 : 0;
        }
    } else {
        int i = (blockIdx.x - ZB) * 256 + threadIdx.x;   // over float2 units
        if (i < CH * CH / 2) {
            float2 v = ((const float2*)W)[i];
            __half2 a = __floats2half2_rn(v.x, v.y);
            ((unsigned int*)g_w16)[i] = *(unsigned int*)&a;
        }
    }
}

// ---------------- CSR build (2 edges per thread) ----------------
__global__ void k_degree(const void* __restrict__ ei) {
    int i = blockIdx.x * blockDim.x + threadIdx.x;   // pair index
    if (i < N_EDGES / 2) {
        int d0, d1;
        if (g_idx64) {
            longlong2 v = ((const longlong2*)((const long long*)ei + N_EDGES))[i];
            d0 = (int)v.x; d1 = (int)v.y;
        } else {
            int2 v = ((const int2*)((const int*)ei + N_EDGES))[i];
            d0 = v.x; d1 = v.y;
        }
        if (d0 >= 0 && d0 < N_NODES) atomicAdd(&g_deg[d0], 1);
        if (d1 >= 0 && d1 < N_NODES) atomicAdd(&g_deg[d1], 1);
    }
}

__global__ void __launch_bounds__(1024) k_scan1() {
    int i = blockIdx.x * 1024 + threadIdx.x;
    int v = (i < N_NODES) ? g_deg[i] : 0;
#pragma unroll
    for (int o = 16; o; o >>= 1) v += __shfl_down_sync(0xffffffffu, v, o);
    __shared__ int ws[32];
    if ((threadIdx.x & 31) == 0) ws[threadIdx.x >> 5] = v;
    __syncthreads();
    if (threadIdx.x < 32) {
        int s = ws[threadIdx.x];
#pragma unroll
        for (int o = 16; o; o >>= 1) s += __shfl_down_sync(0xffffffffu, s, o);
        if (threadIdx.x == 0) g_part[blockIdx.x] = s;
    }
}

__global__ void k_scan2() {
    int t = threadIdx.x;  // 128 threads
    __shared__ int sm[128];
    int v = (t < N_SBLKS) ? g_part[t] : 0;
    sm[t] = v;
    __syncthreads();
    for (int o = 1; o < 128; o <<= 1) {
        int u = (t >= o) ? sm[t - o] : 0;
        __syncthreads();
        sm[t] += u;
        __syncthreads();
    }
    g_part[t] = sm[t] - v;
    if (t == 127) g_off[N_NODES] = sm[127];
}

__global__ void __launch_bounds__(1024) k_scan3() {
    int b = blockIdx.x, t = threadIdx.x;
    int i = b * 1024 + t;
    int lane = t & 31, w = t >> 5;
    int v = (i < N_NODES) ? g_deg[i] : 0;
    int s = v;
#pragma unroll
    for (int o = 1; o < 32; o <<= 1) {
        int u = __shfl_up_sync(0xffffffffu, s, o);
        if (lane >= o) s += u;
    }
    __shared__ int wsum[32];
    if (lane == 31) wsum[w] = s;
    __syncthreads();
    if (w == 0) {
        int ss = wsum[lane];
#pragma unroll
        for (int o = 1; o < 32; o <<= 1) {
            int u = __shfl_up_sync(0xffffffffu, ss, o);
            if (lane >= o) ss += u;
        }
        wsum[lane] = ss;
    }
    __syncthreads();
    int excl = (s - v) + ((w > 0) ? wsum[w - 1] : 0) + g_part[b];
    if (i < N_NODES) {
        g_off[i] = excl;
        g_cursor[i] = excl;
    }
}

__global__ void k_fill(const void* __restrict__ ei) {
    int i = blockIdx.x * blockDim.x + threadIdx.x;   // pair index
    if (i < N_EDGES / 2) {
        int s0, s1, d0, d1;
        if (g_idx64) {
            const long long* e64 = (const long long*)ei;
            longlong2 sv = ((const longlong2*)e64)[i];
            longlong2 dv = ((const longlong2*)(e64 + N_EDGES))[i];
            s0 = (int)sv.x; s1 = (int)sv.y; d0 = (int)dv.x; d1 = (int)dv.y;
        } else {
            const int* e32 = (const int*)ei;
            int2 sv = ((const int2*)e32)[i];
            int2 dv = ((const int2*)(e32 + N_EDGES))[i];
            s0 = sv.x; s1 = sv.y; d0 = dv.x; d1 = dv.y;
        }
        if (s0 >= 0 && s0 < N_NODES && d0 >= 0 && d0 < N_NODES) {
            int p = atomicAdd(&g_cursor[d0], 1);
            g_srcs[p] = s0;
        }
        if (s1 >= 0 && s1 < N_NODES && d1 >= 0 && d1 < N_NODES) {
            int p = atomicAdd(&g_cursor[d1], 1);
            g_srcs[p] = s1;
        }
    }
}

// ---------------- GEMM via tensor cores: y16 = fp16(x @ W^T) ----------------
// x fp32 in gmem (converted during smem fill); W pre-converted in g_w16.
// mma.sync m16n8k16. 128 threads = 4 warps, tile 64 rows x 128 cols, K=128.
// Hs 16KB + Wsm 32KB = 48KB static smem. Rows = 16 chunks of 16B, XOR-swizzled.
#define GBM 64

__global__ void __launch_bounds__(128) k_gemm_x(
    const float* __restrict__ x, __half* __restrict__ y) {
    __shared__ __half Hs[GBM * CH];   // 16 KB (swizzled)
    __shared__ __half Wsm[CH * CH];   // 32 KB (swizzled)

    const int t = threadIdx.x;
    const int warp = t >> 5;
    const int lane = t & 31;
    const int gid = lane >> 2;        // 0..7
    const int tg = lane & 3;          // 0..3
    const int rb = blockIdx.x * GBM;

    // fill Hs from fp32 x: 64 rows x 16 chunks (chunk = 8 halves <- 8 floats)
    for (int i = t; i < GBM * 16; i += 128) {
        int r = i >> 4, c = i & 15;
        int n = rb + r;
        uint4 o = make_uint4(0u, 0u, 0u, 0u);
        if (n < N_NODES) {
            const float4* xr = (const float4*)(x + (size_t)n * CH + c * 8);
            float4 f0 = xr[0];
            float4 f1 = xr[1];
            __half2 h0 = __floats2half2_rn(f0.x, f0.y);
            __half2 h1 = __floats2half2_rn(f0.z, f0.w);
            __half2 h2 = __floats2half2_rn(f1.x, f1.y);
            __half2 h3 = __floats2half2_rn(f1.z, f1.w);
            o.x = *(unsigned*)&h0; o.y = *(unsigned*)&h1;
            o.z = *(unsigned*)&h2; o.w = *(unsigned*)&h3;
        }
        ((uint4*)Hs)[(r << 4) | (c ^ (r & 7))] = o;
    }
    // fill Wsm: 128 rows x 16 chunks
    for (int i = t; i < CH * 16; i += 128) {
        int r = i >> 4, c = i & 15;
        uint4 v = ((const uint4*)g_w16)[i];
        ((uint4*)Wsm)[(r << 4) | (c ^ (r & 7))] = v;
    }
    __syncthreads();

    float acc[16][4];
#pragma unroll
    for (int nt = 0; nt < 16; nt++)
#pragma unroll
        for (int i = 0; i < 4; i++) acc[nt][i] = 0.f;

    const int wr = warp * 16;
    const char* HsB = (const char*)Hs;
    const char* WsB = (const char*)Wsm;

#pragma unroll
    for (int ks = 0; ks < 8; ks++) {
        int rA0 = wr + gid, rA1 = rA0 + 8;
        int cA0 = ks * 2, cA1 = ks * 2 + 1;
        unsigned a0 = *(const unsigned*)(HsB + rA0 * 256 + ((cA0 ^ (rA0 & 7)) << 4) + tg * 4);
        unsigned a1 = *(const unsigned*)(HsB + rA1 * 256 + ((cA0 ^ (rA1 & 7)) << 4) + tg * 4);
        unsigned a2 = *(const unsigned*)(HsB + rA0 * 256 + ((cA1 ^ (rA0 & 7)) << 4) + tg * 4);
        unsigned a3 = *(const unsigned*)(HsB + rA1 * 256 + ((cA1 ^ (rA1 & 7)) << 4) + tg * 4);

#pragma unroll
        for (int nt = 0; nt < 16; nt++) {
            int n = nt * 8 + gid;
            unsigned b0 = *(const unsigned*)(WsB + n * 256 + ((cA0 ^ (n & 7)) << 4) + tg * 4);
            unsigned b1 = *(const unsigned*)(WsB + n * 256 + ((cA1 ^ (n & 7)) << 4) + tg * 4);
            asm volatile(
                "mma.sync.aligned.m16n8k16.row.col.f32.f16.f16.f32 "
                "{%0,%1,%2,%3}, {%4,%5,%6,%7}, {%8,%9}, {%0,%1,%2,%3};"
                : "+f"(acc[nt][0]), "+f"(acc[nt][1]),
                  "+f"(acc[nt][2]), "+f"(acc[nt][3])
                : "r"(a0), "r"(a1), "r"(a2), "r"(a3), "r"(b0), "r"(b1));
        }
    }

    // epilogue: store fp16 y (bias added after hops)
    int row0 = rb + wr + gid;
    int row1 = row0 + 8;
#pragma unroll
    for (int nt = 0; nt < 16; nt++) {
        int col = nt * 8 + 2 * tg;
        if (row0 < N_NODES) {
            __half2 o = __floats2half2_rn(acc[nt][0], acc[nt][1]);
            *(__half2*)(y + (size_t)row0 * CH + col) = o;
        }
        if (row1 < N_NODES) {
            __half2 o = __floats2half2_rn(acc[nt][2], acc[nt][3]);
            *(__half2*)(y + (size_t)row1 * CH + col) = o;
        }
    }
}

// ---------------- mean propagation (fp16 -> fp16), warp per dst node ----------------
__global__ void __launch_bounds__(256) k_hop_mid(const __half* __restrict__ in,
                                                 __half* __restrict__ out) {
    int warp = (blockIdx.x * blockDim.x + threadIdx.x) >> 5;
    int lane = threadIdx.x & 31;
    if (warp >= N_NODES) return;

    int beg = g_off[warp];
    int end = g_off[warp + 1];

    float4 acc[4];
#pragma unroll
    for (int i = 0; i < 4; i++) acc[i] = make_float4(0.f, 0.f, 0.f, 0.f);

    int j = beg;
    for (; j + 3 < end; j += 4) {
        uint2 v[4];
#pragma unroll
        for (int u = 0; u < 4; u++) {
            int s = g_srcs[j + u];
            v[u] = __ldg((const uint2*)(in + (size_t)s * CH) + lane);
        }
#pragma unroll
        for (int u = 0; u < 4; u++) {
            float2 p = __half22float2(*(__half2*)&v[u].x);
            float2 q = __half22float2(*(__half2*)&v[u].y);
            acc[u].x += p.x; acc[u].y += p.y; acc[u].z += q.x; acc[u].w += q.y;
        }
    }
    for (; j < end; j++) {
        int s = g_srcs[j];
        uint2 v0 = __ldg((const uint2*)(in + (size_t)s * CH) + lane);
        float2 p = __half22float2(*(__half2*)&v0.x);
        float2 q = __half22float2(*(__half2*)&v0.y);
        acc[0].x += p.x; acc[0].y += p.y; acc[0].z += q.x; acc[0].w += q.y;
    }

    int d = end - beg;
    float inv = 1.0f / (float)(d > 0 ? d : 1);
    float4 r;
    r.x = (acc[0].x + acc[1].x + acc[2].x + acc[3].x) * inv;
    r.y = (acc[0].y + acc[1].y + acc[2].y + acc[3].y) * inv;
    r.z = (acc[0].z + acc[1].z + acc[2].z + acc[3].z) * inv;
    r.w = (acc[0].w + acc[1].w + acc[2].w + acc[3].w) * inv;
    __half2 r0 = __floats2half2_rn(r.x, r.y);
    __half2 r1 = __floats2half2_rn(r.z, r.w);
    uint2 o;
    o.x = *(unsigned int*)&r0;
    o.y = *(unsigned int*)&r1;
    ((uint2*)(out + (size_t)warp * CH))[lane] = o;
}

// ---------------- final hop: fp16 in -> fp32 out, bias fused ----------------
__global__ void __launch_bounds__(256) k_hop_last(const __half* __restrict__ in,
                                                  const float* __restrict__ bias,
                                                  float* __restrict__ out) {
    int warp = (blockIdx.x * blockDim.x + threadIdx.x) >> 5;
    int lane = threadIdx.x & 31;
    if (warp >= N_NODES) return;

    int beg = g_off[warp];
    int end = g_off[warp + 1];

    float4 acc[4];
#pragma unroll
    for (int i = 0; i < 4; i++) acc[i] = make_float4(0.f, 0.f, 0.f, 0.f);

    int j = beg;
    for (; j + 3 < end; j += 4) {
        uint2 v[4];
#pragma unroll
        for (int u = 0; u < 4; u++) {
            int s = g_srcs[j + u];
            v[u] = __ldg((const uint2*)(in + (size_t)s * CH) + lane);
        }
#pragma unroll
        for (int u = 0; u < 4; u++) {
            float2 p = __half22float2(*(__half2*)&v[u].x);
            float2 q = __half22float2(*(__half2*)&v[u].y);
            acc[u].x += p.x; acc[u].y += p.y; acc[u].z += q.x; acc[u].w += q.y;
        }
    }
    for (; j < end; j++) {
        int s = g_srcs[j];
        uint2 v0 = __ldg((const uint2*)(in + (size_t)s * CH) + lane);
        float2 p = __half22float2(*(__half2*)&v0.x);
        float2 q = __half22float2(*(__half2*)&v0.y);
        acc[0].x += p.x; acc[0].y += p.y; acc[0].z += q.x; acc[0].w += q.y;
    }

    int d = end - beg;
    float inv = 1.0f / (float)(d > 0 ? d : 1);
    float4 bv = __ldg((const float4*)bias + lane);
    float4 r;
    r.x = (acc[0].x + acc[1].x + acc[2].x + acc[3].x) * inv + bv.x;
    r.y = (acc[0].y + acc[1].y + acc[2].y + acc[3].y) * inv + bv.y;
    r.z = (acc[0].z + acc[1].z + acc[2].z + acc[3].z) * inv + bv.z;
    r.w = (acc[0].w + acc[1].w + acc[2].w + acc[3].w) * inv + bv.w;
    ((float4*)(out + (size_t)warp * CH))[lane] = r;
}

// ---------------- launcher (plain kernel launches ONLY) ----------------
extern "C" void kernel_launch(void* const* d_in, const int* in_sizes, int n_in,
                              void* d_out, int out_size) {
    const float* x  = (const float*)d_in[0];
    const void*  ei = d_in[1];   // int32 or int64, detected on device
    const float* W  = (const float*)d_in[2];
    const float* b  = (const float*)d_in[3];
    float*       out = (float*)d_out;

    const int TB = 256;

    __half* y16; __half* h1;
    cudaGetSymbolAddress((void**)&y16, g_y16);
    cudaGetSymbolAddress((void**)&h1, g_h1);

    // prep (zero deg + detect + W->fp16), then CSR build
    k_prep<<<ZB + WB, 256>>>((const int*)ei, W);
    k_degree<<<(N_EDGES / 2 + TB - 1) / TB, TB>>>(ei);
    k_scan1<<<N_SBLKS, 1024>>>();
    k_scan2<<<1, 128>>>();
    k_scan3<<<N_SBLKS, 1024>>>();
    k_fill<<<(N_EDGES / 2 + TB - 1) / TB, TB>>>(ei);

    // y16 = fp16(x @ W^T)  (commutes with propagation)
    k_gemm_x<<<(N_NODES + GBM - 1) / GBM, 128>>>(x, y16);

    // two mean-propagation hops; bias fused into the last one
    int hopBlocks = (N_NODES + 8 - 1) / 8;  // 8 warps/block, warp per node
    k_hop_mid<<<hopBlocks, TB>>>(y16, h1);
    k_hop_last<<<hopBlocks, TB>>>(h1, b, out);
}